// round 1
// baseline (speedup 1.0000x reference)
#include <cuda_runtime.h>

#define BB   8
#define DD   128
#define KK   7
#define QQ   256
#define G0V  511
#define KP   512     // padded K for the big GEMM
#define G1V  512
#define F1V  512
#define F2V  1024
#define OUTC 16

// Scratch (static device arrays — no allocation APIs)
__device__ float g_u[BB * DD * KP];      // relu pre-act, c-part (+g0_b), padded col 511 = 0
__device__ float g_v[BB * DD * KP];      // a-part, padded col 511 = 0
__device__ float g_qc[BB * G1V];         // qst @ g1_w[511:767] + g1_b
__device__ float g_part[BB * DD * G1V];  // per-(b,a) column sums of relu(h1@W + qc)

// ---------------------------------------------------------------------------
// Kernel 1: u[b,i,g] = g0_b[g] + sum_k x[b,i,k]*g0_w[k,g]
//           v[b,i,g] =            sum_k x[b,i,k]*g0_w[k+7,g]
// grid = B*D blocks, 512 threads (thread = g; g==511 writes 0 pad)
// ---------------------------------------------------------------------------
__global__ void prep_uv_kernel(const float* __restrict__ x,
                               const float* __restrict__ g0w,
                               const float* __restrict__ g0b) {
    const int bi = blockIdx.x;          // b*128 + i
    const int g  = threadIdx.x;         // 0..511
    __shared__ float xs[KK];
    if (threadIdx.x < KK) xs[threadIdx.x] = x[bi * KK + threadIdx.x];
    __syncthreads();

    float u = 0.f, v = 0.f;
    if (g < G0V) {
        u = g0b[g];
#pragma unroll
        for (int k = 0; k < KK; ++k) {
            u += xs[k] * g0w[k * G0V + g];
            v += xs[k] * g0w[(k + KK) * G0V + g];
        }
    }
    g_u[bi * KP + g] = u;
    g_v[bi * KP + g] = v;
}

// ---------------------------------------------------------------------------
// Kernel 2: qc[b,n] = g1_b[n] + sum_q qst[b,q] * g1_w[511+q, n]
// grid = B, 512 threads (thread = n)
// ---------------------------------------------------------------------------
__global__ void prep_qc_kernel(const float* __restrict__ qst,
                               const float* __restrict__ g1w,
                               const float* __restrict__ g1b) {
    const int b = blockIdx.x;
    const int n = threadIdx.x;
    __shared__ float qs[QQ];
    if (n < QQ) qs[n] = qst[b * QQ + n];
    __syncthreads();

    float s = g1b[n];
#pragma unroll 4
    for (int q = 0; q < QQ; ++q)
        s += qs[q] * g1w[(G0V + q) * G1V + n];
    g_qc[b * G1V + n] = s;
}

// ---------------------------------------------------------------------------
// Kernel 3 (dominant): per CTA (nt, a, b):
//   C[c, n] = sum_k relu(u[b,c,k]+v[b,a,k]) * g1_w[k, nt*128+n]   (k < 511)
//   part[b,a, nt*128+n] = sum_c relu(C[c,n] + qc[b, nt*128+n])
// 256 threads, thread (tx,ty) owns an 8x8 micro-tile; f32x2 packed FMAs.
// ---------------------------------------------------------------------------
__global__ __launch_bounds__(256, 2) void rn_gemm_kernel(const float* __restrict__ g1w) {
    __shared__ float sm[16 * 133 + 16 * 128];   // As (padded pitch 133) + Bs
    float* As = sm;
    float* Bs = sm + 16 * 133;

    const int t  = threadIdx.x;
    const int tx = t & 15;
    const int ty = t >> 4;
    const int b  = blockIdx.z;
    const int a  = blockIdx.y;
    const int ntbase = blockIdx.x * 128;

    // A-tile load mapping: 128c x 16k, thread loads 8 k for one c
    const int c_ld = t >> 1;
    const int kh   = (t & 1) * 8;
    const float* ubase = g_u + (b * DD + c_ld) * KP;
    const float* vbase = g_v + (b * DD + a) * KP;

    // B-tile load mapping: 16k x 128n, thread loads 8 n for one k
    const int bk = t >> 4;
    const int bn = (t & 15) * 8;

    unsigned long long acc[8][4];
#pragma unroll
    for (int r = 0; r < 8; ++r)
#pragma unroll
        for (int p = 0; p < 4; ++p) acc[r][p] = 0ull;

    for (int k0 = 0; k0 < KP; k0 += 16) {
        __syncthreads();
        // A tile: relu(u + v), padded col 511 is already 0 in both u and v
        {
            float4 u0 = *(const float4*)(ubase + k0 + kh);
            float4 u1 = *(const float4*)(ubase + k0 + kh + 4);
            float4 v0 = *(const float4*)(vbase + k0 + kh);
            float4 v1 = *(const float4*)(vbase + k0 + kh + 4);
            As[(kh + 0) * 133 + c_ld] = fmaxf(u0.x + v0.x, 0.f);
            As[(kh + 1) * 133 + c_ld] = fmaxf(u0.y + v0.y, 0.f);
            As[(kh + 2) * 133 + c_ld] = fmaxf(u0.z + v0.z, 0.f);
            As[(kh + 3) * 133 + c_ld] = fmaxf(u0.w + v0.w, 0.f);
            As[(kh + 4) * 133 + c_ld] = fmaxf(u1.x + v1.x, 0.f);
            As[(kh + 5) * 133 + c_ld] = fmaxf(u1.y + v1.y, 0.f);
            As[(kh + 6) * 133 + c_ld] = fmaxf(u1.z + v1.z, 0.f);
            As[(kh + 7) * 133 + c_ld] = fmaxf(u1.w + v1.w, 0.f);
        }
        // B tile: g1_w rows k0..k0+15 (zero row 511 pad)
        {
            const int gk = k0 + bk;
            float4 w0, w1;
            if (gk < G0V) {
                w0 = *(const float4*)(g1w + gk * G1V + ntbase + bn);
                w1 = *(const float4*)(g1w + gk * G1V + ntbase + bn + 4);
            } else {
                w0 = make_float4(0.f, 0.f, 0.f, 0.f);
                w1 = w0;
            }
            *(float4*)(Bs + bk * 128 + bn)     = w0;
            *(float4*)(Bs + bk * 128 + bn + 4) = w1;
        }
        __syncthreads();

#pragma unroll
        for (int kk = 0; kk < 16; ++kk) {
            unsigned long long a2[8];
#pragma unroll
            for (int r = 0; r < 8; ++r) {
                unsigned int ab = __float_as_uint(As[kk * 133 + ty * 8 + r]);
                asm("mov.b64 %0, {%1, %1};" : "=l"(a2[r]) : "r"(ab));
            }
            unsigned long long b2[4];
#pragma unroll
            for (int p = 0; p < 4; ++p)
                b2[p] = *(const unsigned long long*)(Bs + kk * 128 + tx * 8 + 2 * p);
#pragma unroll
            for (int r = 0; r < 8; ++r)
#pragma unroll
                for (int p = 0; p < 4; ++p)
                    asm("fma.rn.f32x2 %0, %1, %2, %0;"
                        : "+l"(acc[r][p]) : "l"(a2[r]), "l"(b2[p]));
        }
    }

    // Epilogue: +qc, relu, column-sum over this CTA's 128 c rows
    float qcv[8], nsum[8];
#pragma unroll
    for (int j = 0; j < 8; ++j) {
        qcv[j]  = g_qc[b * G1V + ntbase + tx * 8 + j];
        nsum[j] = 0.f;
    }
#pragma unroll
    for (int r = 0; r < 8; ++r) {
#pragma unroll
        for (int p = 0; p < 4; ++p) {
            float lo = __uint_as_float((unsigned int)(acc[r][p] & 0xffffffffull));
            float hi = __uint_as_float((unsigned int)(acc[r][p] >> 32));
            nsum[2 * p]     += fmaxf(lo + qcv[2 * p], 0.f);
            nsum[2 * p + 1] += fmaxf(hi + qcv[2 * p + 1], 0.f);
        }
    }
    __syncthreads();                 // done reading As/Bs; reuse smem
    float* red = sm;                 // 16 x 128
#pragma unroll
    for (int j = 0; j < 8; ++j)
        red[ty * 128 + tx * 8 + j] = nsum[j];
    __syncthreads();
    if (t < 128) {
        float s = 0.f;
#pragma unroll
        for (int w = 0; w < 16; ++w) s += red[w * 128 + t];
        g_part[(b * DD + a) * G1V + ntbase + t] = s;
    }
}

// ---------------------------------------------------------------------------
// Kernel 4: reduce over a, then f1/f2/f3 + log_softmax. grid = B, 512 threads.
// ---------------------------------------------------------------------------
__global__ void finish_kernel(const float* __restrict__ f1w, const float* __restrict__ f1b,
                              const float* __restrict__ f2w, const float* __restrict__ f2b,
                              const float* __restrict__ f3w, const float* __restrict__ f3b,
                              float* __restrict__ out) {
    const int b = blockIdx.x;
    const int t = threadIdx.x;   // 0..511
    __shared__ float xg[G1V];
    __shared__ float h1s[F1V];
    __shared__ float h2s[F2V];
    __shared__ float lp[16 * OUTC];
    __shared__ float lg[OUTC];

    // x_g[b, t] = sum_a part[b,a,t]
    {
        float s = 0.f;
        const float* pp = g_part + b * DD * G1V + t;
#pragma unroll 8
        for (int a = 0; a < DD; ++a) s += pp[a * G1V];
        xg[t] = s;
    }
    __syncthreads();

    // f1 = relu(xg @ f1_w + f1_b)
    {
        float acc = f1b[t];
#pragma unroll 8
        for (int i = 0; i < G1V; ++i) acc += xg[i] * f1w[i * F1V + t];
        h1s[t] = fmaxf(acc, 0.f);
    }
    __syncthreads();

    // f2 = relu(f1 @ f2_w + f2_b)
    for (int jj = t; jj < F2V; jj += 512) {
        float acc = f2b[jj];
#pragma unroll 8
        for (int i = 0; i < F1V; ++i) acc += h1s[i] * f2w[i * F2V + jj];
        h2s[jj] = fmaxf(acc, 0.f);
    }
    __syncthreads();

    // logits = f2 @ f3_w + f3_b (16 outputs, 16 chunks of 64, fixed-order reduce)
    if (t < 256) {
        const int o  = t & 15;
        const int ch = t >> 4;
        float acc = (ch == 0) ? f3b[o] : 0.f;
        for (int i = ch * 64; i < ch * 64 + 64; ++i)
            acc += h2s[i] * f3w[i * OUTC + o];
        lp[ch * OUTC + o] = acc;
    }
    __syncthreads();
    if (t < OUTC) {
        float s = 0.f;
#pragma unroll
        for (int ch = 0; ch < 16; ++ch) s += lp[ch * OUTC + t];
        lg[t] = s;
    }
    __syncthreads();
    if (t < OUTC) {
        float m = lg[0];
#pragma unroll
        for (int i = 1; i < OUTC; ++i) m = fmaxf(m, lg[i]);
        float se = 0.f;
#pragma unroll
        for (int i = 0; i < OUTC; ++i) se += expf(lg[i] - m);
        out[b * OUTC + t] = lg[t] - m - logf(se);
    }
}

// ---------------------------------------------------------------------------
extern "C" void kernel_launch(void* const* d_in, const int* in_sizes, int n_in,
                              void* d_out, int out_size) {
    const float* x    = (const float*)d_in[0];
    const float* qst  = (const float*)d_in[1];
    const float* g0w  = (const float*)d_in[2];
    const float* g0b  = (const float*)d_in[3];
    const float* g1w  = (const float*)d_in[4];
    const float* g1b  = (const float*)d_in[5];
    const float* f1w  = (const float*)d_in[6];
    const float* f1b  = (const float*)d_in[7];
    const float* f2w  = (const float*)d_in[8];
    const float* f2b  = (const float*)d_in[9];
    const float* f3w  = (const float*)d_in[10];
    const float* f3b  = (const float*)d_in[11];
    float* out = (float*)d_out;

    prep_uv_kernel<<<BB * DD, 512>>>(x, g0w, g0b);
    prep_qc_kernel<<<BB, 512>>>(qst, g1w, g1b);
    dim3 grid(G1V / 128, DD, BB);   // (4, 128, 8)
    rn_gemm_kernel<<<grid, 256>>>(g1w);
    finish_kernel<<<BB, 512>>>(f1w, f1b, f2w, f2b, f3w, f3b, out);
}

// round 4
// speedup vs baseline: 3.2035x; 3.2035x over previous
#include <cuda_runtime.h>
#include <cuda_bf16.h>
#include <cstdint>

#define BB   8
#define DD   128
#define KK   7
#define QQ   256
#define G0V  511
#define KP   512
#define G1V  512
#define F1V  512
#define F2V  1024
#define OUTC 16

// ---------------- scratch (static device arrays, no alloc APIs) -------------
__device__ __nv_bfloat16 g_u_bf[BB * DD * KP];   // relu c-part (incl g0_b), col 511 = 0
__device__ __nv_bfloat16 g_v_bf[BB * DD * KP];   // a-part, col 511 = 0
__device__ __nv_bfloat16 g_wt_hi[G1V * KP];      // W^T hi  [n][k], k>=511 = 0
__device__ __nv_bfloat16 g_wt_lo[G1V * KP];      // W^T lo residual
__device__ float g_qc[BB * G1V];                 // qst @ g1_w[511:767] + g1_b
__device__ float g_part[BB * DD * G1V];          // per (b,a) col sums
__device__ float g_xg[BB * G1V];
__device__ float g_h1[BB * F1V];
__device__ float g_h2[BB * F2V];

// ---------------- helpers ----------------------------------------------------
__device__ __forceinline__ uint32_t smem_u32(const void* p) {
    uint32_t a;
    asm("{ .reg .u64 t; cvta.to.shared.u64 t, %1; cvt.u32.u64 %0, t; }" : "=r"(a) : "l"(p));
    return a;
}
__device__ __forceinline__ uint32_t relu_add2(uint32_t ua, uint32_t va) {
    __nv_bfloat162 x = __hadd2(*reinterpret_cast<__nv_bfloat162*>(&ua),
                               *reinterpret_cast<__nv_bfloat162*>(&va));
    x = __hmax2(x, __float2bfloat162_rn(0.f));
    return *reinterpret_cast<uint32_t*>(&x);
}

#define LDMX4(r0, r1, r2, r3, addr) \
    asm volatile("ldmatrix.sync.aligned.m8n8.x4.shared.b16 {%0,%1,%2,%3}, [%4];" \
        : "=r"(r0), "=r"(r1), "=r"(r2), "=r"(r3) : "r"(addr))

#define MMA_BF16(c, A, b0, b1) \
    asm volatile("mma.sync.aligned.m16n8k16.row.col.f32.bf16.bf16.f32 " \
        "{%0,%1,%2,%3},{%4,%5,%6,%7},{%8,%9},{%0,%1,%2,%3};" \
        : "+f"((c)[0]), "+f"((c)[1]), "+f"((c)[2]), "+f"((c)[3]) \
        : "r"((A)[0]), "r"((A)[1]), "r"((A)[2]), "r"((A)[3]), "r"(b0), "r"(b1))

// ---------------- prep kernels ----------------------------------------------
__global__ void prep_uv_kernel(const float* __restrict__ x,
                               const float* __restrict__ g0w,
                               const float* __restrict__ g0b) {
    const int bi = blockIdx.x;          // b*128 + i
    const int g  = threadIdx.x;         // 0..511
    __shared__ float xs[KK];
    if (threadIdx.x < KK) xs[threadIdx.x] = x[bi * KK + threadIdx.x];
    __syncthreads();
    float u = 0.f, v = 0.f;
    if (g < G0V) {
        u = g0b[g];
#pragma unroll
        for (int k = 0; k < KK; ++k) {
            u += xs[k] * g0w[k * G0V + g];
            v += xs[k] * g0w[(k + KK) * G0V + g];
        }
    }
    g_u_bf[bi * KP + g] = __float2bfloat16(u);
    g_v_bf[bi * KP + g] = __float2bfloat16(v);
}

__global__ void prep_w_kernel(const float* __restrict__ g1w) {
    const int n = blockIdx.x;
    for (int k = threadIdx.x; k < KP; k += 256) {
        float w = (k < G0V) ? g1w[k * G1V + n] : 0.f;
        __nv_bfloat16 hi = __float2bfloat16(w);
        float rem = w - __bfloat162float(hi);
        g_wt_hi[n * KP + k] = hi;
        g_wt_lo[n * KP + k] = __float2bfloat16(rem);
    }
}

__global__ void prep_qc_kernel(const float* __restrict__ qst,
                               const float* __restrict__ g1w,
                               const float* __restrict__ g1b) {
    const int b = blockIdx.x;
    const int n = threadIdx.x;
    __shared__ float qs[QQ];
    if (n < QQ) qs[n] = qst[b * QQ + n];
    __syncthreads();
    float s = g1b[n];
#pragma unroll 4
    for (int q = 0; q < QQ; ++q)
        s += qs[q] * g1w[(G0V + q) * G1V + n];
    g_qc[b * G1V + n] = s;
}

// ---------------- the dominant kernel: HMMA GEMM + fused epilogue -----------
// grid = (nq=4, ap=64, b=8); 512 threads = 16 warps (wc 0-3 x wn 0-3).
// CTA: 2 a-values (ap*2, ap*2+1), c = 0..127, n = nq*128..+127, K = 512,
// with W = Whi + Wlo accumulated into the same fp32 accums.
// Epilogue: part[b,a,n] = sum_c relu(D_a[c,n] + qc[b,n]).

#define OFF_V      0          // 2 x 512 bf16 = 2048 B
#define OFF_QC     2048       // 128 f32 = 512 B
#define OFF_RED    2560       // 8 x 128 f32 = 4096 B
#define OFF_STAGE  6784
#define T_PITCH    80         // bytes per 32-half row (64 B data + 16 pad)
#define TILE_SZ    (128 * T_PITCH)      // 10240
#define STAGE_SZ   (4 * TILE_SZ)        // A0 A1 BH BL = 40960
#define SMEM_MMA_TOTAL (OFF_STAGE + 2 * STAGE_SZ)   // 88704

__global__ __launch_bounds__(512, 1) void rn_mma_kernel() {
    extern __shared__ char smem[];
    const uint32_t sbase = smem_u32(smem);
    const int t = threadIdx.x;
    const int lane = t & 31, warp = t >> 5;
    const int wc = warp >> 2, wn = warp & 3;
    const int nq = blockIdx.x, ap = blockIdx.y, b = blockIdx.z;

    // preload v rows (2 a-values, contiguous) + qc slice
    if (t < 128) {
        ((uint4*)smem)[t] =
            ((const uint4*)(g_v_bf + (size_t)(b * DD + ap * 2) * KP))[t];
    } else if (t < 256) {
        ((float*)(smem + OFF_QC))[t - 128] = g_qc[b * G1V + nq * 128 + (t - 128)];
    }
    __syncthreads();

    // ---- build-phase per-thread mapping: row = t/4 (0..127), seg = t%4
    const int row = t >> 2, seg = t & 3;
    const __nv_bfloat16* uptr = g_u_bf + (size_t)(b * DD + row) * KP + seg * 8;
    const __nv_bfloat16* hptr = g_wt_hi + (size_t)(nq * 128 + row) * KP + seg * 8;
    const __nv_bfloat16* lptr = g_wt_lo + (size_t)(nq * 128 + row) * KP + seg * 8;
    const uint32_t arow = (uint32_t)row * T_PITCH + seg * 16;

    auto build = [&](int kb, int s) {
        char* sb = smem + OFF_STAGE + s * STAGE_SZ;
        uint4 uu = *(const uint4*)(uptr + kb * 32);
        uint4 wh = *(const uint4*)(hptr + kb * 32);
        uint4 wl = *(const uint4*)(lptr + kb * 32);
        uint4 v0 = *(const uint4*)(smem + kb * 64 + seg * 16);
        uint4 v1 = *(const uint4*)(smem + 1024 + kb * 64 + seg * 16);
        uint4 a0, a1;
        a0.x = relu_add2(uu.x, v0.x); a0.y = relu_add2(uu.y, v0.y);
        a0.z = relu_add2(uu.z, v0.z); a0.w = relu_add2(uu.w, v0.w);
        a1.x = relu_add2(uu.x, v1.x); a1.y = relu_add2(uu.y, v1.y);
        a1.z = relu_add2(uu.z, v1.z); a1.w = relu_add2(uu.w, v1.w);
        *(uint4*)(sb + arow)               = a0;
        *(uint4*)(sb + TILE_SZ + arow)     = a1;
        *(uint4*)(sb + 2 * TILE_SZ + arow) = wh;
        *(uint4*)(sb + 3 * TILE_SZ + arow) = wl;
    };

    // ---- compute-phase ldmatrix per-lane base offsets
    const int grp = lane >> 3, rin = lane & 7;
    const uint32_t aOff = (uint32_t)(wc * 32 + rin + (grp & 1) * 8) * T_PITCH + (grp >> 1) * 16;
    const uint32_t bOff = (uint32_t)(wn * 32 + rin + (grp >> 1) * 8) * T_PITCH + (grp & 1) * 16;

    float acc[2][2][4][4];
#pragma unroll
    for (int a = 0; a < 2; ++a)
#pragma unroll
        for (int mi = 0; mi < 2; ++mi)
#pragma unroll
            for (int ni = 0; ni < 4; ++ni)
#pragma unroll
                for (int j = 0; j < 4; ++j) acc[a][mi][ni][j] = 0.f;

    build(0, 0);
    __syncthreads();

    for (int it = 0; it < 16; ++it) {
        if (it + 1 < 16) build(it + 1, (it + 1) & 1);
        const uint32_t sb = sbase + OFF_STAGE + (it & 1) * STAGE_SZ;
#pragma unroll
        for (int kk = 0; kk < 2; ++kk) {
            uint32_t BH[4][2], BL[4][2];
            const uint32_t bhA = sb + 2 * TILE_SZ + bOff + kk * 32;
            LDMX4(BH[0][0], BH[0][1], BH[1][0], BH[1][1], bhA);
            LDMX4(BH[2][0], BH[2][1], BH[3][0], BH[3][1], bhA + 16 * T_PITCH);
            const uint32_t blA = sb + 3 * TILE_SZ + bOff + kk * 32;
            LDMX4(BL[0][0], BL[0][1], BL[1][0], BL[1][1], blA);
            LDMX4(BL[2][0], BL[2][1], BL[3][0], BL[3][1], blA + 16 * T_PITCH);
#pragma unroll
            for (int a = 0; a < 2; ++a) {
                uint32_t AF[2][4];
                const uint32_t aa = sb + a * TILE_SZ + aOff + kk * 32;
                LDMX4(AF[0][0], AF[0][1], AF[0][2], AF[0][3], aa);
                LDMX4(AF[1][0], AF[1][1], AF[1][2], AF[1][3], aa + 16 * T_PITCH);
#pragma unroll
                for (int mi = 0; mi < 2; ++mi)
#pragma unroll
                    for (int ni = 0; ni < 4; ++ni) {
                        MMA_BF16(acc[a][mi][ni], AF[mi], BH[ni][0], BH[ni][1]);
                        MMA_BF16(acc[a][mi][ni], AF[mi], BL[ni][0], BL[ni][1]);
                    }
            }
        }
        __syncthreads();
    }

    // ---- epilogue: relu(D + qc), sum over c (deterministic) ----
    const float* qcs = (const float*)(smem + OFF_QC);
    float* red = (float*)(smem + OFF_RED);
    float qn0[4], qn1[4];
    const int nc0 = wn * 32 + (lane & 3) * 2;
#pragma unroll
    for (int ni = 0; ni < 4; ++ni) {
        qn0[ni] = qcs[nc0 + ni * 8];
        qn1[ni] = qcs[nc0 + ni * 8 + 1];
    }
#pragma unroll
    for (int a = 0; a < 2; ++a) {
        float s0[4], s1[4];
#pragma unroll
        for (int ni = 0; ni < 4; ++ni) {
            s0[ni] = 0.f; s1[ni] = 0.f;
#pragma unroll
            for (int mi = 0; mi < 2; ++mi) {
                s0[ni] += fmaxf(acc[a][mi][ni][0] + qn0[ni], 0.f)
                        + fmaxf(acc[a][mi][ni][2] + qn0[ni], 0.f);
                s1[ni] += fmaxf(acc[a][mi][ni][1] + qn1[ni], 0.f)
                        + fmaxf(acc[a][mi][ni][3] + qn1[ni], 0.f);
            }
        }
#pragma unroll
        for (int off = 4; off < 32; off <<= 1)
#pragma unroll
            for (int ni = 0; ni < 4; ++ni) {
                s0[ni] += __shfl_xor_sync(0xffffffffu, s0[ni], off);
                s1[ni] += __shfl_xor_sync(0xffffffffu, s1[ni], off);
            }
        if (lane < 4) {
#pragma unroll
            for (int ni = 0; ni < 4; ++ni) {
                red[(wc * 2 + a) * 128 + wn * 32 + ni * 8 + lane * 2]     = s0[ni];
                red[(wc * 2 + a) * 128 + wn * 32 + ni * 8 + lane * 2 + 1] = s1[ni];
            }
        }
    }
    __syncthreads();
    if (t < 256) {
        const int a = t >> 7, n = t & 127;
        float s = 0.f;
#pragma unroll
        for (int w = 0; w < 4; ++w) s += red[(w * 2 + a) * 128 + n];
        g_part[((size_t)(b * DD) + ap * 2 + a) * G1V + nq * 128 + n] = s;
    }
}

// ---------------- finish: parallel small kernels ----------------------------
__global__ void k_xg(void) {
    const int b = blockIdx.x >> 2, nq = blockIdx.x & 3;
    const int t = threadIdx.x;   // 128
    const float* p = g_part + (size_t)(b * DD) * G1V + nq * 128 + t;
    float s = 0.f;
#pragma unroll 8
    for (int a = 0; a < DD; ++a) s += p[(size_t)a * G1V];
    g_xg[b * G1V + nq * 128 + t] = s;
}

__global__ void k_f1(const float* __restrict__ f1w, const float* __restrict__ f1b) {
    const int nq = blockIdx.x, b = blockIdx.y;
    const int t = threadIdx.x;   // 128
    __shared__ float xs[G1V];
    for (int i = t; i < G1V; i += 128) xs[i] = g_xg[b * G1V + i];
    __syncthreads();
    const int j = nq * 128 + t;
    float acc = f1b[j];
#pragma unroll 8
    for (int i = 0; i < G1V; ++i) acc += xs[i] * f1w[i * F1V + j];
    g_h1[b * F1V + j] = fmaxf(acc, 0.f);
}

__global__ void k_f2(const float* __restrict__ f2w, const float* __restrict__ f2b) {
    const int jb = blockIdx.x, b = blockIdx.y;
    const int t = threadIdx.x;   // 128
    __shared__ float hs[F1V];
    for (int i = t; i < F1V; i += 128) hs[i] = g_h1[b * F1V + i];
    __syncthreads();
    const int j = jb * 128 + t;
    float acc = f2b[j];
#pragma unroll 8
    for (int i = 0; i < F1V; ++i) acc += hs[i] * f2w[i * F2V + j];
    g_h2[b * F2V + j] = fmaxf(acc, 0.f);
}

__global__ void k_f3(const float* __restrict__ f3w, const float* __restrict__ f3b,
                     float* __restrict__ out) {
    const int b = blockIdx.x;
    const int t = threadIdx.x;   // 256
    __shared__ float h2s[F2V];
    __shared__ float lp[16 * OUTC];
    __shared__ float lg[OUTC];
    for (int i = t; i < F2V; i += 256) h2s[i] = g_h2[b * F2V + i];
    __syncthreads();
    {
        const int o  = t & 15;
        const int ch = t >> 4;
        float acc = (ch == 0) ? f3b[o] : 0.f;
        for (int i = ch * 64; i < ch * 64 + 64; ++i)
            acc += h2s[i] * f3w[i * OUTC + o];
        lp[ch * OUTC + o] = acc;
    }
    __syncthreads();
    if (t < OUTC) {
        float s = 0.f;
#pragma unroll
        for (int ch = 0; ch < 16; ++ch) s += lp[ch * OUTC + t];
        lg[t] = s;
    }
    __syncthreads();
    if (t < OUTC) {
        float m = lg[0];
#pragma unroll
        for (int i = 1; i < OUTC; ++i) m = fmaxf(m, lg[i]);
        float se = 0.f;
#pragma unroll
        for (int i = 0; i < OUTC; ++i) se += expf(lg[i] - m);
        out[b * OUTC + t] = lg[t] - m - logf(se);
    }
}

// ---------------- launch -----------------------------------------------------
extern "C" void kernel_launch(void* const* d_in, const int* in_sizes, int n_in,
                              void* d_out, int out_size) {
    const float* x   = (const float*)d_in[0];
    const float* qst = (const float*)d_in[1];
    const float* g0w = (const float*)d_in[2];
    const float* g0b = (const float*)d_in[3];
    const float* g1w = (const float*)d_in[4];
    const float* g1b = (const float*)d_in[5];
    const float* f1w = (const float*)d_in[6];
    const float* f1b = (const float*)d_in[7];
    const float* f2w = (const float*)d_in[8];
    const float* f2b = (const float*)d_in[9];
    const float* f3w = (const float*)d_in[10];
    const float* f3b = (const float*)d_in[11];
    float* out = (float*)d_out;

    static bool attr_set = false;
    if (!attr_set) {
        cudaFuncSetAttribute(rn_mma_kernel,
                             cudaFuncAttributeMaxDynamicSharedMemorySize, SMEM_MMA_TOTAL);
        attr_set = true;
    }

    prep_uv_kernel<<<BB * DD, 512>>>(x, g0w, g0b);
    prep_w_kernel<<<G1V, 256>>>(g1w);
    prep_qc_kernel<<<BB, 512>>>(qst, g1w, g1b);
    rn_mma_kernel<<<dim3(4, 64, BB), 512, SMEM_MMA_TOTAL>>>();
    k_xg<<<32, 128>>>();
    k_f1<<<dim3(4, BB), 128>>>(f1w, f1b);
    k_f2<<<dim3(8, BB), 128>>>(f2w, f2b);
    k_f3<<<BB, 256>>>(f3w, f3b, out);
}

// round 5
// speedup vs baseline: 3.7395x; 1.1673x over previous
#include <cuda_runtime.h>
#include <cuda_bf16.h>
#include <cstdint>

#define BB   8
#define DD   128
#define KK   7
#define QQ   256
#define G0V  511
#define KP   512
#define G1V  512
#define F1V  512
#define F2V  1024
#define OUTC 16

// ---------------- scratch (static device arrays, no alloc APIs) -------------
__device__ __nv_bfloat16 g_u_bf[BB * DD * KP];   // relu c-part (incl g0_b), col 511 = 0
__device__ __nv_bfloat16 g_v_bf[BB * DD * KP];   // a-part, col 511 = 0
__device__ __nv_bfloat16 g_wt_hi[G1V * KP];      // W^T hi  [n][k], k>=511 = 0
__device__ __nv_bfloat16 g_wt_lo[G1V * KP];      // W^T lo residual
__device__ float g_qc[BB * G1V];                 // qst @ g1_w[511:767] + g1_b
__device__ float g_part[BB * DD * G1V];          // per (b,a) col sums
__device__ float g_h1[BB * F1V];
__device__ float g_h2[BB * F2V];

// ---------------- helpers ----------------------------------------------------
__device__ __forceinline__ uint32_t smem_u32(const void* p) {
    uint32_t a;
    asm("{ .reg .u64 t; cvta.to.shared.u64 t, %1; cvt.u32.u64 %0, t; }" : "=r"(a) : "l"(p));
    return a;
}
__device__ __forceinline__ uint32_t relu_add2(uint32_t ua, uint32_t va) {
    __nv_bfloat162 x = __hadd2(*reinterpret_cast<__nv_bfloat162*>(&ua),
                               *reinterpret_cast<__nv_bfloat162*>(&va));
    x = __hmax2(x, __float2bfloat162_rn(0.f));
    return *reinterpret_cast<uint32_t*>(&x);
}

#define LDMX4(r0, r1, r2, r3, addr) \
    asm volatile("ldmatrix.sync.aligned.m8n8.x4.shared.b16 {%0,%1,%2,%3}, [%4];" \
        : "=r"(r0), "=r"(r1), "=r"(r2), "=r"(r3) : "r"(addr))

#define MMA_BF16(c, A, b0, b1) \
    asm volatile("mma.sync.aligned.m16n8k16.row.col.f32.bf16.bf16.f32 " \
        "{%0,%1,%2,%3},{%4,%5,%6,%7},{%8,%9},{%0,%1,%2,%3};" \
        : "+f"((c)[0]), "+f"((c)[1]), "+f"((c)[2]), "+f"((c)[3]) \
        : "r"((A)[0]), "r"((A)[1]), "r"((A)[2]), "r"((A)[3]), "r"(b0), "r"(b1))

#define CP_ASYNC16(dst, src) \
    asm volatile("cp.async.cg.shared.global [%0], [%1], 16;" :: "r"(dst), "l"(src) : "memory")
#define CP_COMMIT() asm volatile("cp.async.commit_group;" ::: "memory")
#define CP_WAIT0()  asm volatile("cp.async.wait_group 0;" ::: "memory")

// ---------------- merged prep kernel ----------------------------------------
// grid = 1024 (uv) + 512 (w split) + 8 (qc), 512 threads
__global__ void prep_all_kernel(const float* __restrict__ x,
                                const float* __restrict__ g0w,
                                const float* __restrict__ g0b,
                                const float* __restrict__ g1w,
                                const float* __restrict__ qst,
                                const float* __restrict__ g1b) {
    const int bid = blockIdx.x;
    const int t = threadIdx.x;
    if (bid < BB * DD) {
        // ---- u / v
        __shared__ float xs[KK];
        if (t < KK) xs[t] = x[bid * KK + t];
        __syncthreads();
        float u = 0.f, v = 0.f;
        if (t < G0V) {
            u = g0b[t];
#pragma unroll
            for (int k = 0; k < KK; ++k) {
                u += xs[k] * g0w[k * G0V + t];
                v += xs[k] * g0w[(k + KK) * G0V + t];
            }
        }
        g_u_bf[bid * KP + t] = __float2bfloat16(u);
        g_v_bf[bid * KP + t] = __float2bfloat16(v);
    } else if (bid < BB * DD + G1V) {
        // ---- W^T hi/lo split; thread t = k
        const int n = bid - BB * DD;
        float w = (t < G0V) ? g1w[t * G1V + n] : 0.f;
        __nv_bfloat16 hi = __float2bfloat16(w);
        float rem = w - __bfloat162float(hi);
        g_wt_hi[n * KP + t] = hi;
        g_wt_lo[n * KP + t] = __float2bfloat16(rem);
    } else {
        // ---- qc
        const int b = bid - (BB * DD + G1V);
        __shared__ float qs[QQ];
        if (t < QQ) qs[t] = qst[b * QQ + t];
        __syncthreads();
        float s = g1b[t];
#pragma unroll 4
        for (int q = 0; q < QQ; ++q)
            s += qs[q] * g1w[(G0V + q) * G1V + t];
        g_qc[b * G1V + t] = s;
    }
}

// ---------------- dominant kernel: pipelined HMMA GEMM + fused epilogue -----
// grid = (nq=4, ap=64, b=8); 512 threads = 16 warps (wc 0-3 x wn 0-3).
// CTA: 2 a-values, c = 0..127, n = nq*128..+127, K = 512, W = Whi + Wlo.
// part[b,a,n] = sum_c relu(D_a[c,n] + qc[b,n]).

#define OFF_V      0          // 2 x 512 bf16 = 2048 B
#define OFF_QC     2048       // 128 f32 = 512 B
#define OFF_RED    2560       // 8 x 128 f32 = 4096 B
#define OFF_STAGE  6784
#define T_PITCH    80
#define TILE_SZ    (128 * T_PITCH)      // 10240
#define STAGE_SZ   (4 * TILE_SZ)        // A0 A1 BH BL = 40960
#define SMEM_MMA_TOTAL (OFF_STAGE + 2 * STAGE_SZ)   // 88704

__global__ __launch_bounds__(512, 1) void rn_mma_kernel() {
    extern __shared__ char smem[];
    const uint32_t sbase = smem_u32(smem);
    const int t = threadIdx.x;
    const int lane = t & 31, warp = t >> 5;
    const int wc = warp >> 2, wn = warp & 3;
    const int nq = blockIdx.x, ap = blockIdx.y, b = blockIdx.z;

    // preload v rows (2 a-values) + qc slice
    if (t < 128) {
        ((uint4*)smem)[t] =
            ((const uint4*)(g_v_bf + (size_t)(b * DD + ap * 2) * KP))[t];
    } else if (t < 256) {
        ((float*)(smem + OFF_QC))[t - 128] = g_qc[b * G1V + nq * 128 + (t - 128)];
    }
    __syncthreads();

    // build-phase mapping: row = t/4 (0..127), seg = t%4
    const int row = t >> 2, seg = t & 3;
    const __nv_bfloat16* uptr = g_u_bf + (size_t)(b * DD + row) * KP + seg * 8;
    const __nv_bfloat16* hptr = g_wt_hi + (size_t)(nq * 128 + row) * KP + seg * 8;
    const __nv_bfloat16* lptr = g_wt_lo + (size_t)(nq * 128 + row) * KP + seg * 8;
    const uint32_t arow = (uint32_t)row * T_PITCH + seg * 16;

    // A-build from prefetched u regs + v smem, store to stage s
    auto buildA = [&](int kb, int s, const uint4& uu) {
        char* sb = smem + OFF_STAGE + s * STAGE_SZ;
        uint4 v0 = *(const uint4*)(smem + kb * 64 + seg * 16);
        uint4 v1 = *(const uint4*)(smem + 1024 + kb * 64 + seg * 16);
        uint4 a0, a1;
        a0.x = relu_add2(uu.x, v0.x); a0.y = relu_add2(uu.y, v0.y);
        a0.z = relu_add2(uu.z, v0.z); a0.w = relu_add2(uu.w, v0.w);
        a1.x = relu_add2(uu.x, v1.x); a1.y = relu_add2(uu.y, v1.y);
        a1.z = relu_add2(uu.z, v1.z); a1.w = relu_add2(uu.w, v1.w);
        *(uint4*)(sb + arow)           = a0;
        *(uint4*)(sb + TILE_SZ + arow) = a1;
    };

    // compute-phase ldmatrix per-lane base offsets
    const int grp = lane >> 3, rin = lane & 7;
    const uint32_t aOff = (uint32_t)(wc * 32 + rin + (grp & 1) * 8) * T_PITCH + (grp >> 1) * 16;
    const uint32_t bOff = (uint32_t)(wn * 32 + rin + (grp >> 1) * 8) * T_PITCH + (grp & 1) * 16;

    float acc[2][2][4][4];
#pragma unroll
    for (int a = 0; a < 2; ++a)
#pragma unroll
        for (int mi = 0; mi < 2; ++mi)
#pragma unroll
            for (int ni = 0; ni < 4; ++ni)
#pragma unroll
                for (int j = 0; j < 4; ++j) acc[a][mi][ni][j] = 0.f;

    // ---- prologue: fill stage 0
    {
        const uint32_t st0 = sbase + OFF_STAGE;
        CP_ASYNC16(st0 + 2 * TILE_SZ + arow, hptr);
        CP_ASYNC16(st0 + 3 * TILE_SZ + arow, lptr);
        CP_COMMIT();
        uint4 uu = *(const uint4*)(uptr);
        buildA(0, 0, uu);
        CP_WAIT0();
    }
    __syncthreads();

    uint4 pu;
    for (int it = 0; it < 16; ++it) {
        const uint32_t sb = sbase + OFF_STAGE + (it & 1) * STAGE_SZ;
        if (it + 1 < 16) {
            const uint32_t nst = sbase + OFF_STAGE + ((it + 1) & 1) * STAGE_SZ;
            CP_ASYNC16(nst + 2 * TILE_SZ + arow, hptr + (it + 1) * 32);
            CP_ASYNC16(nst + 3 * TILE_SZ + arow, lptr + (it + 1) * 32);
            CP_COMMIT();
            pu = *(const uint4*)(uptr + (it + 1) * 32);
        }
#pragma unroll
        for (int kk = 0; kk < 2; ++kk) {
            uint32_t BH[4][2], BL[4][2];
            const uint32_t bhA = sb + 2 * TILE_SZ + bOff + kk * 32;
            LDMX4(BH[0][0], BH[0][1], BH[1][0], BH[1][1], bhA);
            LDMX4(BH[2][0], BH[2][1], BH[3][0], BH[3][1], bhA + 16 * T_PITCH);
            const uint32_t blA = sb + 3 * TILE_SZ + bOff + kk * 32;
            LDMX4(BL[0][0], BL[0][1], BL[1][0], BL[1][1], blA);
            LDMX4(BL[2][0], BL[2][1], BL[3][0], BL[3][1], blA + 16 * T_PITCH);
#pragma unroll
            for (int a = 0; a < 2; ++a) {
                uint32_t AF[2][4];
                const uint32_t aa = sb + a * TILE_SZ + aOff + kk * 32;
                LDMX4(AF[0][0], AF[0][1], AF[0][2], AF[0][3], aa);
                LDMX4(AF[1][0], AF[1][1], AF[1][2], AF[1][3], aa + 16 * T_PITCH);
#pragma unroll
                for (int mi = 0; mi < 2; ++mi)
#pragma unroll
                    for (int ni = 0; ni < 4; ++ni) {
                        MMA_BF16(acc[a][mi][ni], AF[mi], BH[ni][0], BH[ni][1]);
                        MMA_BF16(acc[a][mi][ni], AF[mi], BL[ni][0], BL[ni][1]);
                    }
            }
        }
        if (it + 1 < 16) {
            buildA(it + 1, (it + 1) & 1, pu);
            CP_WAIT0();
        }
        __syncthreads();
    }

    // ---- epilogue: relu(D + qc), sum over c (deterministic) ----
    const float* qcs = (const float*)(smem + OFF_QC);
    float* red = (float*)(smem + OFF_RED);
    float qn0[4], qn1[4];
    const int nc0 = wn * 32 + (lane & 3) * 2;
#pragma unroll
    for (int ni = 0; ni < 4; ++ni) {
        qn0[ni] = qcs[nc0 + ni * 8];
        qn1[ni] = qcs[nc0 + ni * 8 + 1];
    }
#pragma unroll
    for (int a = 0; a < 2; ++a) {
        float s0[4], s1[4];
#pragma unroll
        for (int ni = 0; ni < 4; ++ni) {
            s0[ni] = 0.f; s1[ni] = 0.f;
#pragma unroll
            for (int mi = 0; mi < 2; ++mi) {
                s0[ni] += fmaxf(acc[a][mi][ni][0] + qn0[ni], 0.f)
                        + fmaxf(acc[a][mi][ni][2] + qn0[ni], 0.f);
                s1[ni] += fmaxf(acc[a][mi][ni][1] + qn1[ni], 0.f)
                        + fmaxf(acc[a][mi][ni][3] + qn1[ni], 0.f);
            }
        }
#pragma unroll
        for (int off = 4; off < 32; off <<= 1)
#pragma unroll
            for (int ni = 0; ni < 4; ++ni) {
                s0[ni] += __shfl_xor_sync(0xffffffffu, s0[ni], off);
                s1[ni] += __shfl_xor_sync(0xffffffffu, s1[ni], off);
            }
        if (lane < 4) {
#pragma unroll
            for (int ni = 0; ni < 4; ++ni) {
                red[(wc * 2 + a) * 128 + wn * 32 + ni * 8 + lane * 2]     = s0[ni];
                red[(wc * 2 + a) * 128 + wn * 32 + ni * 8 + lane * 2 + 1] = s1[ni];
            }
        }
    }
    __syncthreads();
    if (t < 256) {
        const int a = t >> 7, n = t & 127;
        float s = 0.f;
#pragma unroll
        for (int w = 0; w < 4; ++w) s += red[(w * 2 + a) * 128 + n];
        g_part[((size_t)(b * DD) + ap * 2 + a) * G1V + nq * 128 + n] = s;
    }
}

// ---------------- finish kernels ---------------------------------------------
// k_f1: each CTA (nq, b) recomputes full xg[b] then its 128 f1 outputs.
__global__ void k_f1(const float* __restrict__ f1w, const float* __restrict__ f1b) {
    const int nq = blockIdx.x, b = blockIdx.y;
    const int t = threadIdx.x;   // 128
    __shared__ float xs[G1V];
    for (int i = t; i < G1V; i += 128) {
        float s = 0.f;
        const float* p = g_part + (size_t)(b * DD) * G1V + i;
#pragma unroll 8
        for (int a = 0; a < DD; ++a) s += p[(size_t)a * G1V];
        xs[i] = s;
    }
    __syncthreads();
    const int j = nq * 128 + t;
    float acc = f1b[j];
#pragma unroll 8
    for (int i = 0; i < G1V; ++i) acc += xs[i] * f1w[i * F1V + j];
    g_h1[b * F1V + j] = fmaxf(acc, 0.f);
}

__global__ void k_f2(const float* __restrict__ f2w, const float* __restrict__ f2b) {
    const int jb = blockIdx.x, b = blockIdx.y;
    const int t = threadIdx.x;   // 128
    __shared__ float hs[F1V];
    for (int i = t; i < F1V; i += 128) hs[i] = g_h1[b * F1V + i];
    __syncthreads();
    const int j = jb * 128 + t;
    float acc = f2b[j];
#pragma unroll 8
    for (int i = 0; i < F1V; ++i) acc += hs[i] * f2w[i * F2V + j];
    g_h2[b * F2V + j] = fmaxf(acc, 0.f);
}

__global__ void k_f3(const float* __restrict__ f3w, const float* __restrict__ f3b,
                     float* __restrict__ out) {
    const int b = blockIdx.x;
    const int t = threadIdx.x;   // 256
    __shared__ float h2s[F2V];
    __shared__ float lp[16 * OUTC];
    __shared__ float lg[OUTC];
    for (int i = t; i < F2V; i += 256) h2s[i] = g_h2[b * F2V + i];
    __syncthreads();
    {
        const int o  = t & 15;
        const int ch = t >> 4;
        float acc = (ch == 0) ? f3b[o] : 0.f;
        for (int i = ch * 64; i < ch * 64 + 64; ++i)
            acc += h2s[i] * f3w[i * OUTC + o];
        lp[ch * OUTC + o] = acc;
    }
    __syncthreads();
    if (t < OUTC) {
        float s = 0.f;
#pragma unroll
        for (int ch = 0; ch < 16; ++ch) s += lp[ch * OUTC + t];
        lg[t] = s;
    }
    __syncthreads();
    if (t < OUTC) {
        float m = lg[0];
#pragma unroll
        for (int i = 1; i < OUTC; ++i) m = fmaxf(m, lg[i]);
        float se = 0.f;
#pragma unroll
        for (int i = 0; i < OUTC; ++i) se += expf(lg[i] - m);
        out[b * OUTC + t] = lg[t] - m - logf(se);
    }
}

// ---------------- launch -----------------------------------------------------
extern "C" void kernel_launch(void* const* d_in, const int* in_sizes, int n_in,
                              void* d_out, int out_size) {
    const float* x   = (const float*)d_in[0];
    const float* qst = (const float*)d_in[1];
    const float* g0w = (const float*)d_in[2];
    const float* g0b = (const float*)d_in[3];
    const float* g1w = (const float*)d_in[4];
    const float* g1b = (const float*)d_in[5];
    const float* f1w = (const float*)d_in[6];
    const float* f1b = (const float*)d_in[7];
    const float* f2w = (const float*)d_in[8];
    const float* f2b = (const float*)d_in[9];
    const float* f3w = (const float*)d_in[10];
    const float* f3b = (const float*)d_in[11];
    float* out = (float*)d_out;

    static bool attr_set = false;
    if (!attr_set) {
        cudaFuncSetAttribute(rn_mma_kernel,
                             cudaFuncAttributeMaxDynamicSharedMemorySize, SMEM_MMA_TOTAL);
        attr_set = true;
    }

    prep_all_kernel<<<BB * DD + G1V + BB, 512>>>(x, g0w, g0b, g1w, qst, g1b);
    rn_mma_kernel<<<dim3(4, 64, BB), 512, SMEM_MMA_TOTAL>>>();
    k_f1<<<dim3(4, BB), 128>>>(f1w, f1b);
    k_f2<<<dim3(8, BB), 128>>>(f2w, f2b);
    k_f3<<<BB, 256>>>(f3w, f3b, out);
}

// round 6
// speedup vs baseline: 3.8170x; 1.0207x over previous
#include <cuda_runtime.h>
#include <cuda_bf16.h>
#include <cstdint>

#define BB   8
#define DD   128
#define KK   7
#define QQ   256
#define G0V  511
#define KP   512
#define G1V  512
#define F1V  512
#define F2V  1024
#define OUTC 16

// ---------------- scratch (static device arrays, no alloc APIs) -------------
__device__ __nv_bfloat16 g_u_bf[BB * DD * KP];   // relu c-part (incl g0_b), col 511 = 0
__device__ __nv_bfloat16 g_v_bf[BB * DD * KP];   // a-part, col 511 = 0
__device__ __nv_bfloat16 g_wt_hi[G1V * KP];      // W^T hi  [n][k], k>=511 = 0
__device__ __nv_bfloat16 g_wt_lo[G1V * KP];      // W^T lo residual
__device__ float g_qc[BB * G1V];                 // qst @ g1_w[511:767] + g1_b
__device__ float g_part[BB * DD * G1V];          // per (b,a) col sums
__device__ float g_xg[BB * G1V];
__device__ float g_h1[BB * F1V];
__device__ float g_h2[BB * F2V];

// ---------------- helpers ----------------------------------------------------
__device__ __forceinline__ uint32_t smem_u32(const void* p) {
    uint32_t a;
    asm("{ .reg .u64 t; cvta.to.shared.u64 t, %1; cvt.u32.u64 %0, t; }" : "=r"(a) : "l"(p));
    return a;
}
__device__ __forceinline__ uint32_t relu_add2(uint32_t ua, uint32_t va) {
    __nv_bfloat162 x = __hadd2(*reinterpret_cast<__nv_bfloat162*>(&ua),
                               *reinterpret_cast<__nv_bfloat162*>(&va));
    x = __hmax2(x, __float2bfloat162_rn(0.f));
    return *reinterpret_cast<uint32_t*>(&x);
}

#define LDMX4(r0, r1, r2, r3, addr) \
    asm volatile("ldmatrix.sync.aligned.m8n8.x4.shared.b16 {%0,%1,%2,%3}, [%4];" \
        : "=r"(r0), "=r"(r1), "=r"(r2), "=r"(r3) : "r"(addr))

#define MMA_BF16(c, A, b0, b1) \
    asm volatile("mma.sync.aligned.m16n8k16.row.col.f32.bf16.bf16.f32 " \
        "{%0,%1,%2,%3},{%4,%5,%6,%7},{%8,%9},{%0,%1,%2,%3};" \
        : "+f"((c)[0]), "+f"((c)[1]), "+f"((c)[2]), "+f"((c)[3]) \
        : "r"((A)[0]), "r"((A)[1]), "r"((A)[2]), "r"((A)[3]), "r"(b0), "r"(b1))

#define CP_ASYNC16(dst, src) \
    asm volatile("cp.async.cg.shared.global [%0], [%1], 16;" :: "r"(dst), "l"(src) : "memory")
#define CP_COMMIT() asm volatile("cp.async.commit_group;" ::: "memory")
#define CP_WAIT1()  asm volatile("cp.async.wait_group 1;" ::: "memory")

// ---------------- merged prep kernel ----------------------------------------
__global__ void prep_all_kernel(const float* __restrict__ x,
                                const float* __restrict__ g0w,
                                const float* __restrict__ g0b,
                                const float* __restrict__ g1w,
                                const float* __restrict__ qst,
                                const float* __restrict__ g1b) {
    const int bid = blockIdx.x;
    const int t = threadIdx.x;
    if (bid < BB * DD) {
        __shared__ float xs[KK];
        if (t < KK) xs[t] = x[bid * KK + t];
        __syncthreads();
        float u = 0.f, v = 0.f;
        if (t < G0V) {
            u = g0b[t];
#pragma unroll
            for (int k = 0; k < KK; ++k) {
                u += xs[k] * g0w[k * G0V + t];
                v += xs[k] * g0w[(k + KK) * G0V + t];
            }
        }
        g_u_bf[bid * KP + t] = __float2bfloat16(u);
        g_v_bf[bid * KP + t] = __float2bfloat16(v);
    } else if (bid < BB * DD + G1V) {
        const int n = bid - BB * DD;
        float w = (t < G0V) ? g1w[t * G1V + n] : 0.f;
        __nv_bfloat16 hi = __float2bfloat16(w);
        float rem = w - __bfloat162float(hi);
        g_wt_hi[n * KP + t] = hi;
        g_wt_lo[n * KP + t] = __float2bfloat16(rem);
    } else {
        const int b = bid - (BB * DD + G1V);
        __shared__ float qs[QQ];
        if (t < QQ) qs[t] = qst[b * QQ + t];
        __syncthreads();
        float s = g1b[t];
#pragma unroll 4
        for (int q = 0; q < QQ; ++q)
            s += qs[q] * g1w[(G0V + q) * G1V + t];
        g_qc[b * G1V + t] = s;
    }
}

// ---------------- dominant kernel: 3-stage pipelined HMMA GEMM --------------
// grid = (nq=4, ap=64, b=8); 512 threads = 16 warps (wc 0-3 x wn 0-3).
// CTA: 2 a-values, c = 0..127, n = nq*128..+127, K = 512, W = Whi + Wlo.
// part[b,a,n] = sum_c relu(D_a[c,n] + qc[b,n]).

#define OFF_V      0          // 2 x 512 bf16 = 2048 B
#define OFF_QC     2048       // 128 f32 = 512 B
#define OFF_RED    2560       // 8 x 128 f32 = 4096 B
#define OFF_STAGE  6784
#define T_PITCH    80
#define TILE_SZ    (128 * T_PITCH)      // 10240
#define STAGE_SZ   (4 * TILE_SZ)        // A0 A1 BH BL = 40960
#define NSTAGE     3
#define SMEM_MMA_TOTAL (OFF_STAGE + NSTAGE * STAGE_SZ)   // 129664

__global__ __launch_bounds__(512, 1) void rn_mma_kernel() {
    extern __shared__ char smem[];
    const uint32_t sbase = smem_u32(smem);
    const int t = threadIdx.x;
    const int lane = t & 31, warp = t >> 5;
    const int wc = warp >> 2, wn = warp & 3;
    const int nq = blockIdx.x, ap = blockIdx.y, b = blockIdx.z;

    // preload v rows (2 a-values) + qc slice
    if (t < 128) {
        ((uint4*)smem)[t] =
            ((const uint4*)(g_v_bf + (size_t)(b * DD + ap * 2) * KP))[t];
    } else if (t < 256) {
        ((float*)(smem + OFF_QC))[t - 128] = g_qc[b * G1V + nq * 128 + (t - 128)];
    }

    // build-phase mapping: row = t/4 (0..127), seg = t%4
    const int row = t >> 2, seg = t & 3;
    const __nv_bfloat16* uptr = g_u_bf + (size_t)(b * DD + row) * KP + seg * 8;
    const __nv_bfloat16* hptr = g_wt_hi + (size_t)(nq * 128 + row) * KP + seg * 8;
    const __nv_bfloat16* lptr = g_wt_lo + (size_t)(nq * 128 + row) * KP + seg * 8;
    const uint32_t arow = (uint32_t)row * T_PITCH + seg * 16;

    auto stAddr = [&](int s) { return sbase + OFF_STAGE + s * STAGE_SZ; };

    auto buildA = [&](int kb, int s, const uint4& uu) {
        char* sb = smem + OFF_STAGE + s * STAGE_SZ;
        uint4 v0 = *(const uint4*)(smem + kb * 64 + seg * 16);
        uint4 v1 = *(const uint4*)(smem + 1024 + kb * 64 + seg * 16);
        uint4 a0, a1;
        a0.x = relu_add2(uu.x, v0.x); a0.y = relu_add2(uu.y, v0.y);
        a0.z = relu_add2(uu.z, v0.z); a0.w = relu_add2(uu.w, v0.w);
        a1.x = relu_add2(uu.x, v1.x); a1.y = relu_add2(uu.y, v1.y);
        a1.z = relu_add2(uu.z, v1.z); a1.w = relu_add2(uu.w, v1.w);
        *(uint4*)(sb + arow)           = a0;
        *(uint4*)(sb + TILE_SZ + arow) = a1;
    };

    // compute-phase ldmatrix per-lane base offsets
    const int grp = lane >> 3, rin = lane & 7;
    const uint32_t aOff = (uint32_t)(wc * 32 + rin + (grp & 1) * 8) * T_PITCH + (grp >> 1) * 16;
    const uint32_t bOff = (uint32_t)(wn * 32 + rin + (grp >> 1) * 8) * T_PITCH + (grp & 1) * 16;

    float acc[2][2][4][4];
#pragma unroll
    for (int a = 0; a < 2; ++a)
#pragma unroll
        for (int mi = 0; mi < 2; ++mi)
#pragma unroll
            for (int ni = 0; ni < 4; ++ni)
#pragma unroll
                for (int j = 0; j < 4; ++j) acc[a][mi][ni][j] = 0.f;

    // ---- prologue: W(0), W(1) in flight; A(0) built; wait W(0)
    CP_ASYNC16(stAddr(0) + 2 * TILE_SZ + arow, hptr);
    CP_ASYNC16(stAddr(0) + 3 * TILE_SZ + arow, lptr);
    CP_COMMIT();
    CP_ASYNC16(stAddr(1) + 2 * TILE_SZ + arow, hptr + 32);
    CP_ASYNC16(stAddr(1) + 3 * TILE_SZ + arow, lptr + 32);
    CP_COMMIT();
    __syncthreads();   // v smem ready before buildA reads it
    {
        uint4 uu = *(const uint4*)(uptr);
        buildA(0, 0, uu);
    }
    CP_WAIT1();        // W(0) complete
    __syncthreads();

    uint4 pu;
    for (int it = 0; it < 16; ++it) {
        const uint32_t sb = stAddr(it % NSTAGE);
        if (it + 2 < 16) {
            const uint32_t nst = stAddr((it + 2) % NSTAGE);
            CP_ASYNC16(nst + 2 * TILE_SZ + arow, hptr + (it + 2) * 32);
            CP_ASYNC16(nst + 3 * TILE_SZ + arow, lptr + (it + 2) * 32);
        }
        CP_COMMIT();   // one group per iteration (possibly empty)
        if (it + 1 < 16) pu = *(const uint4*)(uptr + (it + 1) * 32);

#pragma unroll
        for (int kk = 0; kk < 2; ++kk) {
            uint32_t BH[4][2], BL[4][2];
            const uint32_t bhA = sb + 2 * TILE_SZ + bOff + kk * 32;
            LDMX4(BH[0][0], BH[0][1], BH[1][0], BH[1][1], bhA);
            LDMX4(BH[2][0], BH[2][1], BH[3][0], BH[3][1], bhA + 16 * T_PITCH);
            const uint32_t blA = sb + 3 * TILE_SZ + bOff + kk * 32;
            LDMX4(BL[0][0], BL[0][1], BL[1][0], BL[1][1], blA);
            LDMX4(BL[2][0], BL[2][1], BL[3][0], BL[3][1], blA + 16 * T_PITCH);
#pragma unroll
            for (int a = 0; a < 2; ++a) {
                uint32_t AF[2][4];
                const uint32_t aa = sb + a * TILE_SZ + aOff + kk * 32;
                LDMX4(AF[0][0], AF[0][1], AF[0][2], AF[0][3], aa);
                LDMX4(AF[1][0], AF[1][1], AF[1][2], AF[1][3], aa + 16 * T_PITCH);
#pragma unroll
                for (int mi = 0; mi < 2; ++mi)
#pragma unroll
                    for (int ni = 0; ni < 4; ++ni) {
                        MMA_BF16(acc[a][mi][ni], AF[mi], BH[ni][0], BH[ni][1]);
                        MMA_BF16(acc[a][mi][ni], AF[mi], BL[ni][0], BL[ni][1]);
                    }
            }
        }
        if (it + 1 < 16) buildA(it + 1, (it + 1) % NSTAGE, pu);
        CP_WAIT1();     // W(it+1) complete before next iteration reads it
        __syncthreads();
    }

    // ---- epilogue: relu(D + qc), sum over c (deterministic) ----
    const float* qcs = (const float*)(smem + OFF_QC);
    float* red = (float*)(smem + OFF_RED);
    float qn0[4], qn1[4];
    const int nc0 = wn * 32 + (lane & 3) * 2;
#pragma unroll
    for (int ni = 0; ni < 4; ++ni) {
        qn0[ni] = qcs[nc0 + ni * 8];
        qn1[ni] = qcs[nc0 + ni * 8 + 1];
    }
#pragma unroll
    for (int a = 0; a < 2; ++a) {
        float s0[4], s1[4];
#pragma unroll
        for (int ni = 0; ni < 4; ++ni) {
            s0[ni] = 0.f; s1[ni] = 0.f;
#pragma unroll
            for (int mi = 0; mi < 2; ++mi) {
                s0[ni] += fmaxf(acc[a][mi][ni][0] + qn0[ni], 0.f)
                        + fmaxf(acc[a][mi][ni][2] + qn0[ni], 0.f);
                s1[ni] += fmaxf(acc[a][mi][ni][1] + qn1[ni], 0.f)
                        + fmaxf(acc[a][mi][ni][3] + qn1[ni], 0.f);
            }
        }
#pragma unroll
        for (int off = 4; off < 32; off <<= 1)
#pragma unroll
            for (int ni = 0; ni < 4; ++ni) {
                s0[ni] += __shfl_xor_sync(0xffffffffu, s0[ni], off);
                s1[ni] += __shfl_xor_sync(0xffffffffu, s1[ni], off);
            }
        if (lane < 4) {
#pragma unroll
            for (int ni = 0; ni < 4; ++ni) {
                red[(wc * 2 + a) * 128 + wn * 32 + ni * 8 + lane * 2]     = s0[ni];
                red[(wc * 2 + a) * 128 + wn * 32 + ni * 8 + lane * 2 + 1] = s1[ni];
            }
        }
    }
    __syncthreads();
    if (t < 256) {
        const int a = t >> 7, n = t & 127;
        float s = 0.f;
#pragma unroll
        for (int w = 0; w < 4; ++w) s += red[(w * 2 + a) * 128 + n];
        g_part[((size_t)(b * DD) + ap * 2 + a) * G1V + nq * 128 + n] = s;
    }
}

// ---------------- tail kernels (split-K, high parallelism) -------------------
// k_xg: grid (4, 8), 128 thr: xg[b, nq*128+t] = sum_a part[b,a,..]
__global__ void k_xg() {
    const int nq = blockIdx.x, b = blockIdx.y;
    const int t = threadIdx.x;   // 128
    const float* p = g_part + (size_t)(b * DD) * G1V + nq * 128 + t;
    float s = 0.f;
#pragma unroll 8
    for (int a = 0; a < DD; ++a) s += p[(size_t)a * G1V];
    g_xg[b * G1V + nq * 128 + t] = s;
}

// k_f1: grid (4, 8), 256 thr; 2 threads per output, K split 256+256.
__global__ void k_f1(const float* __restrict__ f1w, const float* __restrict__ f1b) {
    const int nq = blockIdx.x, b = blockIdx.y;
    const int t = threadIdx.x;   // 256
    __shared__ float xs[G1V];
    __shared__ float red[128];
    xs[t]       = g_xg[b * G1V + t];
    xs[t + 256] = g_xg[b * G1V + t + 256];
    __syncthreads();
    const int j = nq * 128 + (t & 127);
    const int half = t >> 7;
    const int base = half * 256;
    float s = 0.f;
#pragma unroll 8
    for (int i = 0; i < 256; ++i)
        s += xs[base + i] * f1w[(size_t)(base + i) * F1V + j];
    if (!half) red[t] = s;
    __syncthreads();
    if (half)
        g_h1[b * F1V + j] = fmaxf(f1b[j] + red[t & 127] + s, 0.f);
}

// k_f2: grid (8, 8), 256 thr; 2 threads per output, K split 256+256.
__global__ void k_f2(const float* __restrict__ f2w, const float* __restrict__ f2b) {
    const int jb = blockIdx.x, b = blockIdx.y;
    const int t = threadIdx.x;   // 256
    __shared__ float hs[F1V];
    __shared__ float red[128];
    hs[t]       = g_h1[b * F1V + t];
    hs[t + 256] = g_h1[b * F1V + t + 256];
    __syncthreads();
    const int j = jb * 128 + (t & 127);
    const int half = t >> 7;
    const int base = half * 256;
    float s = 0.f;
#pragma unroll 8
    for (int i = 0; i < 256; ++i)
        s += hs[base + i] * f2w[(size_t)(base + i) * F2V + j];
    if (!half) red[t & 127] = s;
    __syncthreads();
    if (half)
        g_h2[b * F2V + j] = fmaxf(f2b[j] + red[t & 127] + s, 0.f);
}

__global__ void k_f3(const float* __restrict__ f3w, const float* __restrict__ f3b,
                     float* __restrict__ out) {
    const int b = blockIdx.x;
    const int t = threadIdx.x;   // 256
    __shared__ float h2s[F2V];
    __shared__ float lp[16 * OUTC];
    __shared__ float lg[OUTC];
    for (int i = t; i < F2V; i += 256) h2s[i] = g_h2[b * F2V + i];
    __syncthreads();
    {
        const int o  = t & 15;
        const int ch = t >> 4;
        float acc = (ch == 0) ? f3b[o] : 0.f;
#pragma unroll 8
        for (int i = ch * 64; i < ch * 64 + 64; ++i)
            acc += h2s[i] * f3w[i * OUTC + o];
        lp[ch * OUTC + o] = acc;
    }
    __syncthreads();
    if (t < OUTC) {
        float s = 0.f;
#pragma unroll
        for (int ch = 0; ch < 16; ++ch) s += lp[ch * OUTC + t];
        lg[t] = s;
    }
    __syncthreads();
    if (t < OUTC) {
        float m = lg[0];
#pragma unroll
        for (int i = 1; i < OUTC; ++i) m = fmaxf(m, lg[i]);
        float se = 0.f;
#pragma unroll
        for (int i = 0; i < OUTC; ++i) se += expf(lg[i] - m);
        out[b * OUTC + t] = lg[t] - m - logf(se);
    }
}

// ---------------- launch -----------------------------------------------------
extern "C" void kernel_launch(void* const* d_in, const int* in_sizes, int n_in,
                              void* d_out, int out_size) {
    const float* x   = (const float*)d_in[0];
    const float* qst = (const float*)d_in[1];
    const float* g0w = (const float*)d_in[2];
    const float* g0b = (const float*)d_in[3];
    const float* g1w = (const float*)d_in[4];
    const float* g1b = (const float*)d_in[5];
    const float* f1w = (const float*)d_in[6];
    const float* f1b = (const float*)d_in[7];
    const float* f2w = (const float*)d_in[8];
    const float* f2b = (const float*)d_in[9];
    const float* f3w = (const float*)d_in[10];
    const float* f3b = (const float*)d_in[11];
    float* out = (float*)d_out;

    static bool attr_set = false;
    if (!attr_set) {
        cudaFuncSetAttribute(rn_mma_kernel,
                             cudaFuncAttributeMaxDynamicSharedMemorySize, SMEM_MMA_TOTAL);
        attr_set = true;
    }

    prep_all_kernel<<<BB * DD + G1V + BB, 512>>>(x, g0w, g0b, g1w, qst, g1b);
    rn_mma_kernel<<<dim3(4, 64, BB), 512, SMEM_MMA_TOTAL>>>();
    k_xg<<<dim3(4, BB), 128>>>();
    k_f1<<<dim3(4, BB), 256>>>(f1w, f1b);
    k_f2<<<dim3(8, BB), 256>>>(f2w, f2b);
    k_f3<<<BB, 256>>>(f3w, f3b, out);
}

// round 7
// speedup vs baseline: 6.7611x; 1.7713x over previous
#include <cuda_runtime.h>
#include <cuda_fp16.h>
#include <cstdint>

#define BB   8
#define DD   128
#define KK   7
#define QQ   256
#define G0V  511
#define KP   512
#define G1V  512
#define F1V  512
#define F2V  1024
#define OUTC 16

// ---------------- scratch (static device arrays, no alloc APIs) -------------
__device__ __half g_u_h[BB * DD * KP];   // c-part (incl g0_b), col 511 = 0
__device__ __half g_v_h[BB * DD * KP];   // a-part, col 511 = 0
__device__ __half g_wt[G1V * KP];        // W^T fp16 [n][k], k>=511 = 0
__device__ float g_qc[BB * G1V];         // qst @ g1_w[511:767] + g1_b
__device__ float g_part[BB * DD * G1V];  // per (b,a) col sums
__device__ float g_xg[BB * G1V];
__device__ float g_h1[BB * F1V];
__device__ float g_h2[BB * F2V];

// ---------------- helpers ----------------------------------------------------
__device__ __forceinline__ uint32_t smem_u32(const void* p) {
    uint32_t a;
    asm("{ .reg .u64 t; cvta.to.shared.u64 t, %1; cvt.u32.u64 %0, t; }" : "=r"(a) : "l"(p));
    return a;
}
__device__ __forceinline__ uint32_t relu_add2h(uint32_t ua, uint32_t va) {
    __half2 x = __hadd2(*reinterpret_cast<__half2*>(&ua),
                        *reinterpret_cast<__half2*>(&va));
    x = __hmax2(x, __float2half2_rn(0.f));
    return *reinterpret_cast<uint32_t*>(&x);
}

#define LDMX4(r0, r1, r2, r3, addr) \
    asm volatile("ldmatrix.sync.aligned.m8n8.x4.shared.b16 {%0,%1,%2,%3}, [%4];" \
        : "=r"(r0), "=r"(r1), "=r"(r2), "=r"(r3) : "r"(addr))

#define MMA_F16(c, A, b0, b1) \
    asm volatile("mma.sync.aligned.m16n8k16.row.col.f32.f16.f16.f32 " \
        "{%0,%1,%2,%3},{%4,%5,%6,%7},{%8,%9},{%0,%1,%2,%3};" \
        : "+f"((c)[0]), "+f"((c)[1]), "+f"((c)[2]), "+f"((c)[3]) \
        : "r"((A)[0]), "r"((A)[1]), "r"((A)[2]), "r"((A)[3]), "r"(b0), "r"(b1))

#define CP_ASYNC16(dst, src) \
    asm volatile("cp.async.cg.shared.global [%0], [%1], 16;" :: "r"(dst), "l"(src) : "memory")
#define CP_COMMIT() asm volatile("cp.async.commit_group;" ::: "memory")
#define CP_WAIT1()  asm volatile("cp.async.wait_group 1;" ::: "memory")

// ---------------- merged prep kernel ----------------------------------------
__global__ void prep_all_kernel(const float* __restrict__ x,
                                const float* __restrict__ g0w,
                                const float* __restrict__ g0b,
                                const float* __restrict__ g1w,
                                const float* __restrict__ qst,
                                const float* __restrict__ g1b) {
    const int bid = blockIdx.x;
    const int t = threadIdx.x;
    if (bid < BB * DD) {
        __shared__ float xs[KK];
        if (t < KK) xs[t] = x[bid * KK + t];
        __syncthreads();
        float u = 0.f, v = 0.f;
        if (t < G0V) {
            u = g0b[t];
#pragma unroll
            for (int k = 0; k < KK; ++k) {
                u += xs[k] * g0w[k * G0V + t];
                v += xs[k] * g0w[(k + KK) * G0V + t];
            }
        }
        g_u_h[bid * KP + t] = __float2half(u);
        g_v_h[bid * KP + t] = __float2half(v);
    } else if (bid < BB * DD + G1V) {
        const int n = bid - BB * DD;
        float w = (t < G0V) ? g1w[t * G1V + n] : 0.f;
        g_wt[n * KP + t] = __float2half(w);
    } else {
        const int b = bid - (BB * DD + G1V);
        __shared__ float qs[QQ];
        if (t < QQ) qs[t] = qst[b * QQ + t];
        __syncthreads();
        float s = g1b[t];
#pragma unroll 4
        for (int q = 0; q < QQ; ++q)
            s += qs[q] * g1w[(G0V + q) * G1V + t];
        g_qc[b * G1V + t] = s;
    }
}

// ---------------- dominant kernel: 3-stage pipelined HMMA GEMM (fp16) -------
// grid = (nq=4, ap=64, b=8); 512 threads = 16 warps (wc 0-3 x wn 0-3).
// CTA: 2 a-values, c = 0..127, n = nq*128..+127, K = 512.
// part[b,a,n] = sum_c relu(D_a[c,n] + qc[b,n]).

#define OFF_V      0          // 2 x 512 fp16 = 2048 B
#define OFF_QC     2048       // 128 f32 = 512 B
#define OFF_RED    2560       // 8 x 128 f32 = 4096 B
#define OFF_STAGE  6784
#define T_PITCH    80
#define TILE_SZ    (128 * T_PITCH)      // 10240
#define STAGE_SZ   (3 * TILE_SZ)        // A0 A1 W = 30720
#define NSTAGE     3
#define SMEM_MMA_TOTAL (OFF_STAGE + NSTAGE * STAGE_SZ)   // 98944

__global__ __launch_bounds__(512, 1) void rn_mma_kernel() {
    extern __shared__ char smem[];
    const uint32_t sbase = smem_u32(smem);
    const int t = threadIdx.x;
    const int lane = t & 31, warp = t >> 5;
    const int wc = warp >> 2, wn = warp & 3;
    const int nq = blockIdx.x, ap = blockIdx.y, b = blockIdx.z;

    // preload v rows (2 a-values) + qc slice
    if (t < 128) {
        ((uint4*)smem)[t] =
            ((const uint4*)(g_v_h + (size_t)(b * DD + ap * 2) * KP))[t];
    } else if (t < 256) {
        ((float*)(smem + OFF_QC))[t - 128] = g_qc[b * G1V + nq * 128 + (t - 128)];
    }

    // build-phase mapping: row = t/4 (0..127), seg = t%4
    const int row = t >> 2, seg = t & 3;
    const __half* uptr = g_u_h + (size_t)(b * DD + row) * KP + seg * 8;
    const __half* wptr = g_wt  + (size_t)(nq * 128 + row) * KP + seg * 8;
    const uint32_t arow = (uint32_t)row * T_PITCH + seg * 16;

    auto stAddr = [&](int s) { return sbase + OFF_STAGE + s * STAGE_SZ; };

    auto buildA = [&](int kb, int s, const uint4& uu) {
        char* sb = smem + OFF_STAGE + s * STAGE_SZ;
        uint4 v0 = *(const uint4*)(smem + kb * 64 + seg * 16);
        uint4 v1 = *(const uint4*)(smem + 1024 + kb * 64 + seg * 16);
        uint4 a0, a1;
        a0.x = relu_add2h(uu.x, v0.x); a0.y = relu_add2h(uu.y, v0.y);
        a0.z = relu_add2h(uu.z, v0.z); a0.w = relu_add2h(uu.w, v0.w);
        a1.x = relu_add2h(uu.x, v1.x); a1.y = relu_add2h(uu.y, v1.y);
        a1.z = relu_add2h(uu.z, v1.z); a1.w = relu_add2h(uu.w, v1.w);
        *(uint4*)(sb + arow)           = a0;
        *(uint4*)(sb + TILE_SZ + arow) = a1;
    };

    // compute-phase ldmatrix per-lane base offsets
    const int grp = lane >> 3, rin = lane & 7;
    const uint32_t aOff = (uint32_t)(wc * 32 + rin + (grp & 1) * 8) * T_PITCH + (grp >> 1) * 16;
    const uint32_t bOff = (uint32_t)(wn * 32 + rin + (grp >> 1) * 8) * T_PITCH + (grp & 1) * 16;

    float acc[2][2][4][4];
#pragma unroll
    for (int a = 0; a < 2; ++a)
#pragma unroll
        for (int mi = 0; mi < 2; ++mi)
#pragma unroll
            for (int ni = 0; ni < 4; ++ni)
#pragma unroll
                for (int j = 0; j < 4; ++j) acc[a][mi][ni][j] = 0.f;

    // ---- prologue: W(0), W(1) in flight; A(0) built; wait W(0)
    CP_ASYNC16(stAddr(0) + 2 * TILE_SZ + arow, wptr);
    CP_COMMIT();
    CP_ASYNC16(stAddr(1) + 2 * TILE_SZ + arow, wptr + 32);
    CP_COMMIT();
    __syncthreads();   // v smem ready before buildA reads it
    {
        uint4 uu = *(const uint4*)(uptr);
        buildA(0, 0, uu);
    }
    CP_WAIT1();        // W(0) complete
    __syncthreads();

    uint4 pu;
    for (int it = 0; it < 16; ++it) {
        const uint32_t sb = stAddr(it % NSTAGE);
        if (it + 2 < 16) {
            const uint32_t nst = stAddr((it + 2) % NSTAGE);
            CP_ASYNC16(nst + 2 * TILE_SZ + arow, wptr + (it + 2) * 32);
        }
        CP_COMMIT();   // one group per iteration (possibly empty)
        if (it + 1 < 16) pu = *(const uint4*)(uptr + (it + 1) * 32);

#pragma unroll
        for (int kk = 0; kk < 2; ++kk) {
            uint32_t BW[4][2];
            const uint32_t bwA = sb + 2 * TILE_SZ + bOff + kk * 32;
            LDMX4(BW[0][0], BW[0][1], BW[1][0], BW[1][1], bwA);
            LDMX4(BW[2][0], BW[2][1], BW[3][0], BW[3][1], bwA + 16 * T_PITCH);
#pragma unroll
            for (int a = 0; a < 2; ++a) {
                uint32_t AF[2][4];
                const uint32_t aa = sb + a * TILE_SZ + aOff + kk * 32;
                LDMX4(AF[0][0], AF[0][1], AF[0][2], AF[0][3], aa);
                LDMX4(AF[1][0], AF[1][1], AF[1][2], AF[1][3], aa + 16 * T_PITCH);
#pragma unroll
                for (int mi = 0; mi < 2; ++mi)
#pragma unroll
                    for (int ni = 0; ni < 4; ++ni)
                        MMA_F16(acc[a][mi][ni], AF[mi], BW[ni][0], BW[ni][1]);
            }
        }
        if (it + 1 < 16) buildA(it + 1, (it + 1) % NSTAGE, pu);
        CP_WAIT1();     // W(it+1) complete before next iteration reads it
        __syncthreads();
    }

    // ---- epilogue: relu(D + qc), sum over c (deterministic) ----
    const float* qcs = (const float*)(smem + OFF_QC);
    float* red = (float*)(smem + OFF_RED);
    float qn0[4], qn1[4];
    const int nc0 = wn * 32 + (lane & 3) * 2;
#pragma unroll
    for (int ni = 0; ni < 4; ++ni) {
        qn0[ni] = qcs[nc0 + ni * 8];
        qn1[ni] = qcs[nc0 + ni * 8 + 1];
    }
#pragma unroll
    for (int a = 0; a < 2; ++a) {
        float s0[4], s1[4];
#pragma unroll
        for (int ni = 0; ni < 4; ++ni) {
            s0[ni] = 0.f; s1[ni] = 0.f;
#pragma unroll
            for (int mi = 0; mi < 2; ++mi) {
                s0[ni] += fmaxf(acc[a][mi][ni][0] + qn0[ni], 0.f)
                        + fmaxf(acc[a][mi][ni][2] + qn0[ni], 0.f);
                s1[ni] += fmaxf(acc[a][mi][ni][1] + qn1[ni], 0.f)
                        + fmaxf(acc[a][mi][ni][3] + qn1[ni], 0.f);
            }
        }
#pragma unroll
        for (int off = 4; off < 32; off <<= 1)
#pragma unroll
            for (int ni = 0; ni < 4; ++ni) {
                s0[ni] += __shfl_xor_sync(0xffffffffu, s0[ni], off);
                s1[ni] += __shfl_xor_sync(0xffffffffu, s1[ni], off);
            }
        if (lane < 4) {
#pragma unroll
            for (int ni = 0; ni < 4; ++ni) {
                red[(wc * 2 + a) * 128 + wn * 32 + ni * 8 + lane * 2]     = s0[ni];
                red[(wc * 2 + a) * 128 + wn * 32 + ni * 8 + lane * 2 + 1] = s1[ni];
            }
        }
    }
    __syncthreads();
    if (t < 256) {
        const int a = t >> 7, n = t & 127;
        float s = 0.f;
#pragma unroll
        for (int w = 0; w < 4; ++w) s += red[(w * 2 + a) * 128 + n];
        g_part[((size_t)(b * DD) + ap * 2 + a) * G1V + nq * 128 + n] = s;
    }
}

// ---------------- tail kernels (4-way split-K) -------------------------------
// k_xg: grid (4 nq, 8 b), 512 thr; 4 threads/output over a-chunks of 32.
__global__ void k_xg() {
    const int nq = blockIdx.x, b = blockIdx.y;
    const int t = threadIdx.x;   // 512
    const int n = t & 127, aq = t >> 7;
    __shared__ float red[512];
    const float* p = g_part + ((size_t)(b * DD) + aq * 32) * G1V + nq * 128 + n;
    float s = 0.f;
#pragma unroll
    for (int a = 0; a < 32; ++a) s += p[(size_t)a * G1V];
    red[aq * 128 + n] = s;
    __syncthreads();
    if (t < 128)
        g_xg[b * G1V + nq * 128 + t] =
            red[t] + red[128 + t] + red[256 + t] + red[384 + t];
}

// k_f1: grid (4 nq, 8 b), 512 thr; 4 threads/output, K split 4x128.
__global__ void k_f1(const float* __restrict__ f1w, const float* __restrict__ f1b) {
    const int nq = blockIdx.x, b = blockIdx.y;
    const int t = threadIdx.x;   // 512
    __shared__ float xs[G1V];
    __shared__ float red[512];
    xs[t] = g_xg[b * G1V + t];
    __syncthreads();
    const int j = nq * 128 + (t & 127);
    const int q = t >> 7, base = q * 128;
    float s = 0.f;
#pragma unroll 8
    for (int i = 0; i < 128; ++i)
        s += xs[base + i] * f1w[(size_t)(base + i) * F1V + j];
    red[t] = s;
    __syncthreads();
    if (t < 128)
        g_h1[b * F1V + nq * 128 + t] =
            fmaxf(f1b[nq * 128 + t] + red[t] + red[128 + t] + red[256 + t] + red[384 + t], 0.f);
}

// k_f2: grid (8 jb, 8 b), 512 thr; 4 threads/output, K split 4x128.
__global__ void k_f2(const float* __restrict__ f2w, const float* __restrict__ f2b) {
    const int jb = blockIdx.x, b = blockIdx.y;
    const int t = threadIdx.x;   // 512
    __shared__ float hs[F1V];
    __shared__ float red[512];
    hs[t] = g_h1[b * F1V + t];
    __syncthreads();
    const int j = jb * 128 + (t & 127);
    const int q = t >> 7, base = q * 128;
    float s = 0.f;
#pragma unroll 8
    for (int i = 0; i < 128; ++i)
        s += hs[base + i] * f2w[(size_t)(base + i) * F2V + j];
    red[t] = s;
    __syncthreads();
    if (t < 128)
        g_h2[b * F2V + jb * 128 + t] =
            fmaxf(f2b[jb * 128 + t] + red[t] + red[128 + t] + red[256 + t] + red[384 + t], 0.f);
}

__global__ void k_f3(const float* __restrict__ f3w, const float* __restrict__ f3b,
                     float* __restrict__ out) {
    const int b = blockIdx.x;
    const int t = threadIdx.x;   // 256
    __shared__ float h2s[F2V];
    __shared__ float lp[16 * OUTC];
    __shared__ float lg[OUTC];
    for (int i = t; i < F2V; i += 256) h2s[i] = g_h2[b * F2V + i];
    __syncthreads();
    {
        const int o  = t & 15;
        const int ch = t >> 4;
        float acc = (ch == 0) ? f3b[o] : 0.f;
#pragma unroll 8
        for (int i = ch * 64; i < ch * 64 + 64; ++i)
            acc += h2s[i] * f3w[i * OUTC + o];
        lp[ch * OUTC + o] = acc;
    }
    __syncthreads();
    if (t < OUTC) {
        float s = 0.f;
#pragma unroll
        for (int ch = 0; ch < 16; ++ch) s += lp[ch * OUTC + t];
        lg[t] = s;
    }
    __syncthreads();
    if (t < OUTC) {
        float m = lg[0];
#pragma unroll
        for (int i = 1; i < OUTC; ++i) m = fmaxf(m, lg[i]);
        float se = 0.f;
#pragma unroll
        for (int i = 0; i < OUTC; ++i) se += expf(lg[i] - m);
        out[b * OUTC + t] = lg[t] - m - logf(se);
    }
}

// ---------------- launch -----------------------------------------------------
extern "C" void kernel_launch(void* const* d_in, const int* in_sizes, int n_in,
                              void* d_out, int out_size) {
    const float* x   = (const float*)d_in[0];
    const float* qst = (const float*)d_in[1];
    const float* g0w = (const float*)d_in[2];
    const float* g0b = (const float*)d_in[3];
    const float* g1w = (const float*)d_in[4];
    const float* g1b = (const float*)d_in[5];
    const float* f1w = (const float*)d_in[6];
    const float* f1b = (const float*)d_in[7];
    const float* f2w = (const float*)d_in[8];
    const float* f2b = (const float*)d_in[9];
    const float* f3w = (const float*)d_in[10];
    const float* f3b = (const float*)d_in[11];
    float* out = (float*)d_out;

    static bool attr_set = false;
    if (!attr_set) {
        cudaFuncSetAttribute(rn_mma_kernel,
                             cudaFuncAttributeMaxDynamicSharedMemorySize, SMEM_MMA_TOTAL);
        attr_set = true;
    }

    prep_all_kernel<<<BB * DD + G1V + BB, 512>>>(x, g0w, g0b, g1w, qst, g1b);
    rn_mma_kernel<<<dim3(4, 64, BB), 512, SMEM_MMA_TOTAL>>>();
    k_xg<<<dim3(4, BB), 512>>>();
    k_f1<<<dim3(4, BB), 512>>>(f1w, f1b);
    k_f2<<<dim3(8, BB), 512>>>(f2w, f2b);
    k_f3<<<BB, 256>>>(f3w, f3b, out);
}